// round 15
// baseline (speedup 1.0000x reference)
#include <cuda_runtime.h>
#include <cuda_bf16.h>
#include <math.h>

// ---------------------------------------------------------------------------
// OutLook Attention. GEMMs via mma.sync tf32 (m16n8k8, double-buffered smem),
// fused softmax+attn (no atomics), gather-fold.
// B=64, H=W=56, DIM=384, HEAD=12, HD=32, K=3, PAD=1, STRIDE=2, OUT_H=28, L=784
// ---------------------------------------------------------------------------

#define Bsz     64
#define Him     56
#define Wim     56
#define DIM     384
#define HEAD    12
#define HD      32
#define KK      3
#define OUTH    28
#define LWIN    (OUTH * OUTH)          // 784
#define HWpix   (Him * Wim)            // 3136
#define NLOG    (HEAD * KK * KK * KK * KK)  // 972
#define SCALE   0.17677669529663687f   // 32^-0.5

#define M_BIG   (Bsz * HWpix)          // 200704
#define M_POOL  (Bsz * LWIN)           // 50176

// ----- scratch (device globals: allocation-free) ---------------------------
__device__ float g_V [(size_t)M_BIG  * DIM];        // value image   [B, HW, DIM]
__device__ float g_XP[(size_t)M_POOL * DIM];        // pooled feats  [B, L,  DIM]
__device__ float g_A [(size_t)M_POOL * NLOG];       // attn logits   [B, L,  972]
__device__ float g_O [(size_t)M_POOL * 9 * DIM];    // per-window out [B, L, 9, DIM]
__device__ float g_YF[(size_t)M_BIG  * DIM];        // folded output [B, HW, DIM]

// ---------------------------------------------------------------------------
// TF32 tensor-core GEMM: C[M,N] = A[M,K] * B[N,K]^T + bias[N]
// Block tile 128x128x32, 8 warps (2 M x 4 N), warp tile 64x32.
// Double-buffered dynamic smem (64 KB), one barrier per k-tile.
// Smem tiles stored in fragment order -> conflict-free LDS.128 / LDS.64.
// Requires: M % 128 == 0, K % 32 == 0. N edge predicated.
// ---------------------------------------------------------------------------

__device__ __forceinline__ unsigned f2tf32(float f) {
    unsigned r;
    asm("cvt.rna.tf32.f32 %0, %1;" : "=r"(r) : "f"(f));
    return r;
}

__device__ __forceinline__ void mma_tf32(float c[4],
                                         const unsigned a[4],
                                         const unsigned b[2]) {
    asm volatile(
        "mma.sync.aligned.m16n8k8.row.col.f32.tf32.tf32.f32 "
        "{%0,%1,%2,%3}, {%4,%5,%6,%7}, {%8,%9}, {%0,%1,%2,%3};"
        : "+f"(c[0]), "+f"(c[1]), "+f"(c[2]), "+f"(c[3])
        : "r"(a[0]), "r"(a[1]), "r"(a[2]), "r"(a[3]),
          "r"(b[0]), "r"(b[1]));
}

#define GBM 128
#define GBN 128
#define GBK 32
#define GEMM_SMEM_BYTES (2 * 8192 * 4)   // 2 buffers x (4096 A + 4096 B) words

__global__ __launch_bounds__(256, 1)
void gemm_tf32_kernel(const float* __restrict__ A,
                      const float* __restrict__ B,
                      const float* __restrict__ bias,
                      float* __restrict__ C,
                      int M, int N, int K)
{
    extern __shared__ unsigned smem_dyn[];   // [2][8192]: sA 4096 + sB 4096

    const int tid  = threadIdx.x;
    const int lane = tid & 31;
    const int warp = tid >> 5;
    const int wm   = warp >> 2;          // 0..1  (M warp)
    const int wn   = warp & 3;           // 0..3  (N warp)
    const int g    = lane >> 2;          // groupID
    const int t    = lane & 3;           // thread-in-group
    const int bm   = blockIdx.y * GBM;
    const int bn   = blockIdx.x * GBN;

    float acc[4][4][4];
#pragma unroll
    for (int i = 0; i < 4; i++)
#pragma unroll
        for (int j = 0; j < 4; j++)
#pragma unroll
            for (int e = 0; e < 4; e++) acc[i][j][e] = 0.f;

    // staging registers (software pipeline across syncthreads)
    float4 va[4], vb[4];
    int rA[4], cA[4];
#pragma unroll
    for (int it = 0; it < 4; it++) {
        int f = tid + it * 256;
        rA[it] = f >> 3;
        cA[it] = (f & 7) << 2;
    }

    const int KT = K / GBK;

    // ---- prologue: load first tiles into registers ----
#pragma unroll
    for (int it = 0; it < 4; it++) {
        va[it] = *reinterpret_cast<const float4*>(
            &A[(size_t)(bm + rA[it]) * K + cA[it]]);
        if (bn + rA[it] < N)
            vb[it] = *reinterpret_cast<const float4*>(
                &B[(size_t)(bn + rA[it]) * K + cA[it]]);
        else
            vb[it] = make_float4(0.f, 0.f, 0.f, 0.f);
    }

    for (int kt = 0; kt < KT; kt++) {
        unsigned* sA = smem_dyn + (kt & 1) * 8192;
        unsigned* sB = sA + 4096;

        // ---- stage regs -> smem (fragment order, tf32 convert) ----
#pragma unroll
        for (int it = 0; it < 4; it++) {
            int r = rA[it], c4 = cA[it];
            int kstep = c4 >> 3;
            int kh    = (c4 >> 2) & 1;
            {
                int mtile = r >> 4;
                int gg    = r & 7;
                int rh    = (r >> 3) & 1;
                unsigned base = ((kstep * 8 + mtile) * 32 + gg * 4) * 4 + kh * 2 + rh;
                sA[base +  0] = f2tf32(va[it].x);
                sA[base +  4] = f2tf32(va[it].y);
                sA[base +  8] = f2tf32(va[it].z);
                sA[base + 12] = f2tf32(va[it].w);
            }
            {
                int ntile = r >> 3;
                int gg    = r & 7;
                unsigned base = ((kstep * 16 + ntile) * 32 + gg * 4) * 2 + kh;
                sB[base + 0] = f2tf32(vb[it].x);
                sB[base + 2] = f2tf32(vb[it].y);
                sB[base + 4] = f2tf32(vb[it].z);
                sB[base + 6] = f2tf32(vb[it].w);
            }
        }
        __syncthreads();

        // ---- prefetch next gmem tile (overlaps compute below) ----
        if (kt + 1 < KT) {
            int k0 = (kt + 1) * GBK;
#pragma unroll
            for (int it = 0; it < 4; it++) {
                va[it] = *reinterpret_cast<const float4*>(
                    &A[(size_t)(bm + rA[it]) * K + k0 + cA[it]]);
                if (bn + rA[it] < N)
                    vb[it] = *reinterpret_cast<const float4*>(
                        &B[(size_t)(bn + rA[it]) * K + k0 + cA[it]]);
                else
                    vb[it] = make_float4(0.f, 0.f, 0.f, 0.f);
            }
        }

        // ---- compute: 4 k-steps of m16n8k8 ----
#pragma unroll
        for (int s = 0; s < 4; s++) {
            unsigned af[4][4];
            unsigned bf[4][2];
#pragma unroll
            for (int mt = 0; mt < 4; mt++) {
                const uint4 v = *reinterpret_cast<const uint4*>(
                    &sA[((s * 8 + wm * 4 + mt) * 32 + lane) * 4]);
                af[mt][0] = v.x; af[mt][1] = v.y; af[mt][2] = v.z; af[mt][3] = v.w;
            }
#pragma unroll
            for (int nt = 0; nt < 4; nt++) {
                const uint2 v = *reinterpret_cast<const uint2*>(
                    &sB[((s * 16 + wn * 4 + nt) * 32 + lane) * 2]);
                bf[nt][0] = v.x; bf[nt][1] = v.y;
            }
#pragma unroll
            for (int mt = 0; mt < 4; mt++)
#pragma unroll
                for (int nt = 0; nt < 4; nt++)
                    mma_tf32(acc[mt][nt], af[mt], bf[nt]);
        }
        // no second barrier: next iter stages into the other buffer; its
        // __syncthreads orders reuse of this buffer after all reads.
    }

    // ---- epilogue ----
#pragma unroll
    for (int mt = 0; mt < 4; mt++) {
        int row0 = bm + wm * 64 + mt * 16 + g;
#pragma unroll
        for (int nt = 0; nt < 4; nt++) {
            int col = bn + wn * 32 + nt * 8 + 2 * t;
            if (col < N) {
                float bx = 0.f, by = 0.f;
                if (bias) { bx = __ldg(&bias[col]); by = __ldg(&bias[col + 1]); }
                float2 v0 = make_float2(acc[mt][nt][0] + bx, acc[mt][nt][1] + by);
                float2 v1 = make_float2(acc[mt][nt][2] + bx, acc[mt][nt][3] + by);
                *reinterpret_cast<float2*>(&C[(size_t)row0 * N + col])       = v0;
                *reinterpret_cast<float2*>(&C[(size_t)(row0 + 8) * N + col]) = v1;
            }
        }
    }
}

// ---------------------------------------------------------------------------
// 2x2 average pool: x [B, HW, DIM] -> xp [B, L, DIM]
// ---------------------------------------------------------------------------
__global__ void pool_kernel(const float* __restrict__ x, float* __restrict__ xp)
{
    size_t idx = (size_t)blockIdx.x * blockDim.x + threadIdx.x;
    const size_t total = (size_t)M_POOL * DIM;
    if (idx >= total) return;
    int d = (int)(idx % DIM);
    size_t r = idx / DIM;
    int l = (int)(r % LWIN);
    int b = (int)(r / LWIN);
    int oh = l / OUTH, ow = l % OUTH;
    int h = oh * 2, w = ow * 2;
    const float* xb = x + (size_t)b * HWpix * DIM;
    float s = xb[((size_t)(h    ) * Wim + w    ) * DIM + d]
            + xb[((size_t)(h    ) * Wim + w + 1) * DIM + d]
            + xb[((size_t)(h + 1) * Wim + w    ) * DIM + d]
            + xb[((size_t)(h + 1) * Wim + w + 1) * DIM + d];
    xp[idx] = 0.25f * s;
}

// ---------------------------------------------------------------------------
// Fused softmax + per-window attention apply. NO atomics:
// writes o[b, l, i, c] = sum_j softmax(A)[head(c), i, j] * V[pix(j), c]
// One block per (b, l). 288 threads = (i in 0..8) x (d in 0..31).
// ---------------------------------------------------------------------------
__global__ __launch_bounds__(288)
void attn_apply_kernel(const float* __restrict__ Alog,
                       const float* __restrict__ V,
                       float* __restrict__ O)
{
    __shared__ float sAt[NLOG];         // 972 (softmaxed in place)
    __shared__ float sV[9 * DIM];       // 3456

    const int bl = blockIdx.x;          // b*784 + l
    const int b  = bl / LWIN;
    const int l  = bl % LWIN;
    const int oh = l / OUTH, ow = l % OUTH;
    const int tid = threadIdx.x;

    const float* arow = Alog + (size_t)bl * NLOG;
    for (int tt = tid; tt < NLOG; tt += 288) sAt[tt] = arow[tt] * SCALE;

    const float* vb = V + (size_t)b * HWpix * DIM;
    for (int tt = tid; tt < 9 * DIM; tt += 288) {
        int j = tt / DIM, c = tt % DIM;
        int di = j / KK, dj = j % KK;
        int h2 = oh * 2 - 1 + di;
        int w2 = ow * 2 - 1 + dj;
        float vv = 0.f;
        if (h2 >= 0 && h2 < Him && w2 >= 0 && w2 < Wim)
            vv = vb[((size_t)h2 * Wim + w2) * DIM + c];
        sV[tt] = vv;
    }
    __syncthreads();

    // softmax over 108 groups of 9
    if (tid < HEAD * 9) {
        float* p = &sAt[tid * 9];
        float v[9], m = -1e30f;
#pragma unroll
        for (int j = 0; j < 9; j++) { v[j] = p[j]; m = fmaxf(m, v[j]); }
        float s = 0.f;
#pragma unroll
        for (int j = 0; j < 9; j++) { v[j] = expf(v[j] - m); s += v[j]; }
        float inv = 1.f / s;
#pragma unroll
        for (int j = 0; j < 9; j++) p[j] = v[j] * inv;
    }
    __syncthreads();

    const int i = tid >> 5;             // 0..8
    const int d = tid & 31;             // 0..31
    float* orow = O + ((size_t)bl * 9 + i) * DIM;

#pragma unroll
    for (int head = 0; head < HEAD; head++) {
        const int c = head * HD + d;
        const float* ar = &sAt[head * 81 + i * 9];
        float acc = 0.f;
#pragma unroll
        for (int j = 0; j < 9; j++)
            acc = fmaf(ar[j], sV[j * DIM + c], acc);
        orow[c] = acc;                  // plain coalesced store
    }
}

// ---------------------------------------------------------------------------
// Gather fold: yf[b, h, w, c] = sum over valid (di,dj) of
//   o[b, oh*28+ow, di*3+dj, c] with oh=(h+1-di)/2, ow=(w+1-dj)/2.
// float4 over c (DIM=384 -> 96 chunks).
// ---------------------------------------------------------------------------
__global__ void fold_kernel(const float* __restrict__ O, float* __restrict__ Yf)
{
    size_t idx = (size_t)blockIdx.x * blockDim.x + threadIdx.x;
    const size_t total = (size_t)M_BIG * (DIM / 4);
    if (idx >= total) return;
    int c4 = (int)(idx % (DIM / 4));
    size_t pix = idx / (DIM / 4);
    int b = (int)(pix / HWpix);
    int p = (int)(pix % HWpix);
    int h = p / Wim, w = p % Wim;

    float4 acc = make_float4(0.f, 0.f, 0.f, 0.f);
    const float* ob = O + (size_t)b * LWIN * 9 * DIM;
#pragma unroll
    for (int di = 0; di < KK; di++) {
        int hh = h + 1 - di;
        if (hh & 1) continue;
        int oh = hh >> 1;
        if (oh < 0 || oh >= OUTH) continue;
#pragma unroll
        for (int dj = 0; dj < KK; dj++) {
            int ww = w + 1 - dj;
            if (ww & 1) continue;
            int ow = ww >> 1;
            if (ow < 0 || ow >= OUTH) continue;
            const float4 v = *reinterpret_cast<const float4*>(
                &ob[((size_t)(oh * OUTH + ow) * 9 + (di * KK + dj)) * DIM + c4 * 4]);
            acc.x += v.x; acc.y += v.y; acc.z += v.z; acc.w += v.w;
        }
    }
    *reinterpret_cast<float4*>(&Yf[idx * 4]) = acc;
}

// ---------------------------------------------------------------------------
// kernel_launch
// inputs: x[64,3136,384], Wv[384,384], Wa[972,384], ba[972], Wp[384,384], bp[384]
// output: y[64,3136,384] fp32
// ---------------------------------------------------------------------------
extern "C" void kernel_launch(void* const* d_in, const int* in_sizes, int n_in,
                              void* d_out, int out_size)
{
    const float* x  = (const float*)d_in[0];
    const float* Wv = (const float*)d_in[1];
    const float* Wa = (const float*)d_in[2];
    const float* ba = (const float*)d_in[3];
    const float* Wp = (const float*)d_in[4];
    const float* bp = (const float*)d_in[5];
    float* out = (float*)d_out;

    float *pV, *pXP, *pA, *pO, *pYF;
    cudaGetSymbolAddress((void**)&pV,  g_V);
    cudaGetSymbolAddress((void**)&pXP, g_XP);
    cudaGetSymbolAddress((void**)&pA,  g_A);
    cudaGetSymbolAddress((void**)&pO,  g_O);
    cudaGetSymbolAddress((void**)&pYF, g_YF);

    cudaFuncSetAttribute(gemm_tf32_kernel,
                         cudaFuncAttributeMaxDynamicSharedMemorySize,
                         GEMM_SMEM_BYTES);

    // GEMM1: V = x @ Wv^T           [200704,384] x [384,384]
    gemm_tf32_kernel<<<dim3(DIM / GBN, M_BIG / GBM), 256, GEMM_SMEM_BYTES>>>(
        x, Wv, nullptr, pV, M_BIG, DIM, DIM);

    // pool: xp = avgpool2x2(x)
    {
        size_t total = (size_t)M_POOL * DIM;
        pool_kernel<<<(unsigned)((total + 255) / 256), 256>>>(x, pXP);
    }

    // GEMM2: logits = xp @ Wa^T + ba   [50176,384] x [384,972]
    gemm_tf32_kernel<<<dim3((NLOG + GBN - 1) / GBN, M_POOL / GBM), 256,
                      GEMM_SMEM_BYTES>>>(
        pXP, Wa, ba, pA, M_POOL, NLOG, DIM);

    // fused softmax + attention apply (writes O, no atomics)
    attn_apply_kernel<<<M_POOL, 288>>>(pA, pV, pO);

    // gather fold: O -> Yf
    {
        size_t total = (size_t)M_BIG * (DIM / 4);
        fold_kernel<<<(unsigned)((total + 255) / 256), 256>>>(pO, pYF);
    }

    // GEMM3: out = Yf @ Wp^T + bp     [200704,384] x [384,384]
    gemm_tf32_kernel<<<dim3(DIM / GBN, M_BIG / GBM), 256, GEMM_SMEM_BYTES>>>(
        pYF, Wp, bp, out, M_BIG, DIM, DIM);
}

// round 16
// speedup vs baseline: 1.0033x; 1.0033x over previous
#include <cuda_runtime.h>
#include <cuda_bf16.h>
#include <math.h>

// ---------------------------------------------------------------------------
// OutLook Attention. GEMMs via mma.sync tf32 (m16n8k8, double-buffered smem),
// fused softmax+attn (no atomics), gather-fold.
// B=64, H=W=56, DIM=384, HEAD=12, HD=32, K=3, PAD=1, STRIDE=2, OUT_H=28, L=784
// ---------------------------------------------------------------------------

#define Bsz     64
#define Him     56
#define Wim     56
#define DIM     384
#define HEAD    12
#define HD      32
#define KK      3
#define OUTH    28
#define LWIN    (OUTH * OUTH)          // 784
#define HWpix   (Him * Wim)            // 3136
#define NLOG    (HEAD * KK * KK * KK * KK)  // 972
#define SCALE   0.17677669529663687f   // 32^-0.5

#define M_BIG   (Bsz * HWpix)          // 200704
#define M_POOL  (Bsz * LWIN)           // 50176

// ----- scratch (device globals: allocation-free) ---------------------------
__device__ float g_V [(size_t)M_BIG  * DIM];        // value image   [B, HW, DIM]
__device__ float g_XP[(size_t)M_POOL * DIM];        // pooled feats  [B, L,  DIM]
__device__ float g_A [(size_t)M_POOL * NLOG];       // attn logits   [B, L,  972]
__device__ float g_O [(size_t)M_POOL * 9 * DIM];    // per-window out [B, L, 9, DIM]
__device__ float g_YF[(size_t)M_BIG  * DIM];        // folded output [B, HW, DIM]

// ---------------------------------------------------------------------------
// TF32 tensor-core GEMM: C[M,N] = A[M,K] * B[N,K]^T + bias[N]
// Block tile 128x128x32, 8 warps (2 M x 4 N), warp tile 64x32.
// Double-buffered dynamic smem (64 KB), one barrier per k-tile.
// Smem tiles stored in fragment order -> conflict-free LDS.128 / LDS.64.
// Requires: M % 128 == 0, K % 32 == 0. N edge predicated.
// ---------------------------------------------------------------------------

__device__ __forceinline__ unsigned f2tf32(float f) {
    unsigned r;
    asm("cvt.rna.tf32.f32 %0, %1;" : "=r"(r) : "f"(f));
    return r;
}

__device__ __forceinline__ void mma_tf32(float c[4],
                                         const unsigned a[4],
                                         const unsigned b[2]) {
    asm volatile(
        "mma.sync.aligned.m16n8k8.row.col.f32.tf32.tf32.f32 "
        "{%0,%1,%2,%3}, {%4,%5,%6,%7}, {%8,%9}, {%0,%1,%2,%3};"
        : "+f"(c[0]), "+f"(c[1]), "+f"(c[2]), "+f"(c[3])
        : "r"(a[0]), "r"(a[1]), "r"(a[2]), "r"(a[3]),
          "r"(b[0]), "r"(b[1]));
}

#define GBM 128
#define GBN 128
#define GBK 32
#define GEMM_SMEM_BYTES (2 * 8192 * 4)   // 2 buffers x (4096 A + 4096 B) words

__global__ __launch_bounds__(256, 1)
void gemm_tf32_kernel(const float* __restrict__ A,
                      const float* __restrict__ B,
                      const float* __restrict__ bias,
                      float* __restrict__ C,
                      int M, int N, int K)
{
    extern __shared__ unsigned smem_dyn[];   // [2][8192]: sA 4096 + sB 4096

    const int tid  = threadIdx.x;
    const int lane = tid & 31;
    const int warp = tid >> 5;
    const int wm   = warp >> 2;          // 0..1  (M warp)
    const int wn   = warp & 3;           // 0..3  (N warp)
    const int g    = lane >> 2;          // groupID
    const int t    = lane & 3;           // thread-in-group
    const int bm   = blockIdx.y * GBM;
    const int bn   = blockIdx.x * GBN;

    float acc[4][4][4];
#pragma unroll
    for (int i = 0; i < 4; i++)
#pragma unroll
        for (int j = 0; j < 4; j++)
#pragma unroll
            for (int e = 0; e < 4; e++) acc[i][j][e] = 0.f;

    // staging registers (software pipeline across syncthreads)
    float4 va[4], vb[4];
    int rA[4], cA[4];
#pragma unroll
    for (int it = 0; it < 4; it++) {
        int f = tid + it * 256;
        rA[it] = f >> 3;
        cA[it] = (f & 7) << 2;
    }

    const int KT = K / GBK;

    // ---- prologue: load first tiles into registers ----
#pragma unroll
    for (int it = 0; it < 4; it++) {
        va[it] = *reinterpret_cast<const float4*>(
            &A[(size_t)(bm + rA[it]) * K + cA[it]]);
        if (bn + rA[it] < N)
            vb[it] = *reinterpret_cast<const float4*>(
                &B[(size_t)(bn + rA[it]) * K + cA[it]]);
        else
            vb[it] = make_float4(0.f, 0.f, 0.f, 0.f);
    }

    for (int kt = 0; kt < KT; kt++) {
        unsigned* sA = smem_dyn + (kt & 1) * 8192;
        unsigned* sB = sA + 4096;

        // ---- stage regs -> smem (fragment order, tf32 convert) ----
#pragma unroll
        for (int it = 0; it < 4; it++) {
            int r = rA[it], c4 = cA[it];
            int kstep = c4 >> 3;
            int kh    = (c4 >> 2) & 1;
            {
                int mtile = r >> 4;
                int gg    = r & 7;
                int rh    = (r >> 3) & 1;
                unsigned base = ((kstep * 8 + mtile) * 32 + gg * 4) * 4 + kh * 2 + rh;
                sA[base +  0] = f2tf32(va[it].x);
                sA[base +  4] = f2tf32(va[it].y);
                sA[base +  8] = f2tf32(va[it].z);
                sA[base + 12] = f2tf32(va[it].w);
            }
            {
                int ntile = r >> 3;
                int gg    = r & 7;
                unsigned base = ((kstep * 16 + ntile) * 32 + gg * 4) * 2 + kh;
                sB[base + 0] = f2tf32(vb[it].x);
                sB[base + 2] = f2tf32(vb[it].y);
                sB[base + 4] = f2tf32(vb[it].z);
                sB[base + 6] = f2tf32(vb[it].w);
            }
        }
        __syncthreads();

        // ---- prefetch next gmem tile (overlaps compute below) ----
        if (kt + 1 < KT) {
            int k0 = (kt + 1) * GBK;
#pragma unroll
            for (int it = 0; it < 4; it++) {
                va[it] = *reinterpret_cast<const float4*>(
                    &A[(size_t)(bm + rA[it]) * K + k0 + cA[it]]);
                if (bn + rA[it] < N)
                    vb[it] = *reinterpret_cast<const float4*>(
                        &B[(size_t)(bn + rA[it]) * K + k0 + cA[it]]);
                else
                    vb[it] = make_float4(0.f, 0.f, 0.f, 0.f);
            }
        }

        // ---- compute: 4 k-steps of m16n8k8 ----
#pragma unroll
        for (int s = 0; s < 4; s++) {
            unsigned af[4][4];
            unsigned bf[4][2];
#pragma unroll
            for (int mt = 0; mt < 4; mt++) {
                const uint4 v = *reinterpret_cast<const uint4*>(
                    &sA[((s * 8 + wm * 4 + mt) * 32 + lane) * 4]);
                af[mt][0] = v.x; af[mt][1] = v.y; af[mt][2] = v.z; af[mt][3] = v.w;
            }
#pragma unroll
            for (int nt = 0; nt < 4; nt++) {
                const uint2 v = *reinterpret_cast<const uint2*>(
                    &sB[((s * 16 + wn * 4 + nt) * 32 + lane) * 2]);
                bf[nt][0] = v.x; bf[nt][1] = v.y;
            }
#pragma unroll
            for (int mt = 0; mt < 4; mt++)
#pragma unroll
                for (int nt = 0; nt < 4; nt++)
                    mma_tf32(acc[mt][nt], af[mt], bf[nt]);
        }
        // no second barrier: next iter stages into the other buffer; its
        // __syncthreads orders reuse of this buffer after all reads.
    }

    // ---- epilogue ----
#pragma unroll
    for (int mt = 0; mt < 4; mt++) {
        int row0 = bm + wm * 64 + mt * 16 + g;
#pragma unroll
        for (int nt = 0; nt < 4; nt++) {
            int col = bn + wn * 32 + nt * 8 + 2 * t;
            if (col < N) {
                float bx = 0.f, by = 0.f;
                if (bias) { bx = __ldg(&bias[col]); by = __ldg(&bias[col + 1]); }
                float2 v0 = make_float2(acc[mt][nt][0] + bx, acc[mt][nt][1] + by);
                float2 v1 = make_float2(acc[mt][nt][2] + bx, acc[mt][nt][3] + by);
                *reinterpret_cast<float2*>(&C[(size_t)row0 * N + col])       = v0;
                *reinterpret_cast<float2*>(&C[(size_t)(row0 + 8) * N + col]) = v1;
            }
        }
    }
}

// ---------------------------------------------------------------------------
// 2x2 average pool: x [B, HW, DIM] -> xp [B, L, DIM]
// ---------------------------------------------------------------------------
__global__ void pool_kernel(const float* __restrict__ x, float* __restrict__ xp)
{
    size_t idx = (size_t)blockIdx.x * blockDim.x + threadIdx.x;
    const size_t total = (size_t)M_POOL * DIM;
    if (idx >= total) return;
    int d = (int)(idx % DIM);
    size_t r = idx / DIM;
    int l = (int)(r % LWIN);
    int b = (int)(r / LWIN);
    int oh = l / OUTH, ow = l % OUTH;
    int h = oh * 2, w = ow * 2;
    const float* xb = x + (size_t)b * HWpix * DIM;
    float s = xb[((size_t)(h    ) * Wim + w    ) * DIM + d]
            + xb[((size_t)(h    ) * Wim + w + 1) * DIM + d]
            + xb[((size_t)(h + 1) * Wim + w    ) * DIM + d]
            + xb[((size_t)(h + 1) * Wim + w + 1) * DIM + d];
    xp[idx] = 0.25f * s;
}

// ---------------------------------------------------------------------------
// Fused softmax + per-window attention apply. NO atomics:
// writes o[b, l, i, c] = sum_j softmax(A)[head(c), i, j] * V[pix(j), c]
// One block per (b, l). 288 threads = (i in 0..8) x (d in 0..31).
// ---------------------------------------------------------------------------
__global__ __launch_bounds__(288)
void attn_apply_kernel(const float* __restrict__ Alog,
                       const float* __restrict__ V,
                       float* __restrict__ O)
{
    __shared__ float sAt[NLOG];         // 972 (softmaxed in place)
    __shared__ float sV[9 * DIM];       // 3456

    const int bl = blockIdx.x;          // b*784 + l
    const int b  = bl / LWIN;
    const int l  = bl % LWIN;
    const int oh = l / OUTH, ow = l % OUTH;
    const int tid = threadIdx.x;

    const float* arow = Alog + (size_t)bl * NLOG;
    for (int tt = tid; tt < NLOG; tt += 288) sAt[tt] = arow[tt] * SCALE;

    const float* vb = V + (size_t)b * HWpix * DIM;
    for (int tt = tid; tt < 9 * DIM; tt += 288) {
        int j = tt / DIM, c = tt % DIM;
        int di = j / KK, dj = j % KK;
        int h2 = oh * 2 - 1 + di;
        int w2 = ow * 2 - 1 + dj;
        float vv = 0.f;
        if (h2 >= 0 && h2 < Him && w2 >= 0 && w2 < Wim)
            vv = vb[((size_t)h2 * Wim + w2) * DIM + c];
        sV[tt] = vv;
    }
    __syncthreads();

    // softmax over 108 groups of 9
    if (tid < HEAD * 9) {
        float* p = &sAt[tid * 9];
        float v[9], m = -1e30f;
#pragma unroll
        for (int j = 0; j < 9; j++) { v[j] = p[j]; m = fmaxf(m, v[j]); }
        float s = 0.f;
#pragma unroll
        for (int j = 0; j < 9; j++) { v[j] = expf(v[j] - m); s += v[j]; }
        float inv = 1.f / s;
#pragma unroll
        for (int j = 0; j < 9; j++) p[j] = v[j] * inv;
    }
    __syncthreads();

    const int i = tid >> 5;             // 0..8
    const int d = tid & 31;             // 0..31
    float* orow = O + ((size_t)bl * 9 + i) * DIM;

#pragma unroll
    for (int head = 0; head < HEAD; head++) {
        const int c = head * HD + d;
        const float* ar = &sAt[head * 81 + i * 9];
        float acc = 0.f;
#pragma unroll
        for (int j = 0; j < 9; j++)
            acc = fmaf(ar[j], sV[j * DIM + c], acc);
        orow[c] = acc;                  // plain coalesced store
    }
}

// ---------------------------------------------------------------------------
// Gather fold: yf[b, h, w, c] = sum over valid (di,dj) of
//   o[b, oh*28+ow, di*3+dj, c] with oh=(h+1-di)/2, ow=(w+1-dj)/2.
// float4 over c (DIM=384 -> 96 chunks).
// ---------------------------------------------------------------------------
__global__ void fold_kernel(const float* __restrict__ O, float* __restrict__ Yf)
{
    size_t idx = (size_t)blockIdx.x * blockDim.x + threadIdx.x;
    const size_t total = (size_t)M_BIG * (DIM / 4);
    if (idx >= total) return;
    int c4 = (int)(idx % (DIM / 4));
    size_t pix = idx / (DIM / 4);
    int b = (int)(pix / HWpix);
    int p = (int)(pix % HWpix);
    int h = p / Wim, w = p % Wim;

    float4 acc = make_float4(0.f, 0.f, 0.f, 0.f);
    const float* ob = O + (size_t)b * LWIN * 9 * DIM;
#pragma unroll
    for (int di = 0; di < KK; di++) {
        int hh = h + 1 - di;
        if (hh & 1) continue;
        int oh = hh >> 1;
        if (oh < 0 || oh >= OUTH) continue;
#pragma unroll
        for (int dj = 0; dj < KK; dj++) {
            int ww = w + 1 - dj;
            if (ww & 1) continue;
            int ow = ww >> 1;
            if (ow < 0 || ow >= OUTH) continue;
            const float4 v = *reinterpret_cast<const float4*>(
                &ob[((size_t)(oh * OUTH + ow) * 9 + (di * KK + dj)) * DIM + c4 * 4]);
            acc.x += v.x; acc.y += v.y; acc.z += v.z; acc.w += v.w;
        }
    }
    *reinterpret_cast<float4*>(&Yf[idx * 4]) = acc;
}

// ---------------------------------------------------------------------------
// kernel_launch
// inputs: x[64,3136,384], Wv[384,384], Wa[972,384], ba[972], Wp[384,384], bp[384]
// output: y[64,3136,384] fp32
// ---------------------------------------------------------------------------
extern "C" void kernel_launch(void* const* d_in, const int* in_sizes, int n_in,
                              void* d_out, int out_size)
{
    const float* x  = (const float*)d_in[0];
    const float* Wv = (const float*)d_in[1];
    const float* Wa = (const float*)d_in[2];
    const float* ba = (const float*)d_in[3];
    const float* Wp = (const float*)d_in[4];
    const float* bp = (const float*)d_in[5];
    float* out = (float*)d_out;

    float *pV, *pXP, *pA, *pO, *pYF;
    cudaGetSymbolAddress((void**)&pV,  g_V);
    cudaGetSymbolAddress((void**)&pXP, g_XP);
    cudaGetSymbolAddress((void**)&pA,  g_A);
    cudaGetSymbolAddress((void**)&pO,  g_O);
    cudaGetSymbolAddress((void**)&pYF, g_YF);

    cudaFuncSetAttribute(gemm_tf32_kernel,
                         cudaFuncAttributeMaxDynamicSharedMemorySize,
                         GEMM_SMEM_BYTES);

    // GEMM1: V = x @ Wv^T           [200704,384] x [384,384]
    gemm_tf32_kernel<<<dim3(DIM / GBN, M_BIG / GBM), 256, GEMM_SMEM_BYTES>>>(
        x, Wv, nullptr, pV, M_BIG, DIM, DIM);

    // pool: xp = avgpool2x2(x)
    {
        size_t total = (size_t)M_POOL * DIM;
        pool_kernel<<<(unsigned)((total + 255) / 256), 256>>>(x, pXP);
    }

    // GEMM2: logits = xp @ Wa^T + ba   [50176,384] x [384,972]
    gemm_tf32_kernel<<<dim3((NLOG + GBN - 1) / GBN, M_POOL / GBM), 256,
                      GEMM_SMEM_BYTES>>>(
        pXP, Wa, ba, pA, M_POOL, NLOG, DIM);

    // fused softmax + attention apply (writes O, no atomics)
    attn_apply_kernel<<<M_POOL, 288>>>(pA, pV, pO);

    // gather fold: O -> Yf
    {
        size_t total = (size_t)M_BIG * (DIM / 4);
        fold_kernel<<<(unsigned)((total + 255) / 256), 256>>>(pO, pYF);
    }

    // GEMM3: out = Yf @ Wp^T + bp     [200704,384] x [384,384]
    gemm_tf32_kernel<<<dim3(DIM / GBN, M_BIG / GBM), 256, GEMM_SMEM_BYTES>>>(
        pYF, Wp, bp, out, M_BIG, DIM, DIM);
}

// round 17
// speedup vs baseline: 1.1534x; 1.1496x over previous
#include <cuda_runtime.h>
#include <cuda_bf16.h>
#include <math.h>

// ---------------------------------------------------------------------------
// OutLook Attention. GEMMs via mma.sync tf32 (m16n8k8, double-buffered smem),
// fused softmax+attn (float4-vectorized, no atomics), gather-fold.
// B=64, H=W=56, DIM=384, HEAD=12, HD=32, K=3, PAD=1, STRIDE=2, OUT_H=28, L=784
// ---------------------------------------------------------------------------

#define Bsz     64
#define Him     56
#define Wim     56
#define DIM     384
#define HEAD    12
#define HD      32
#define KK      3
#define OUTH    28
#define LWIN    (OUTH * OUTH)          // 784
#define HWpix   (Him * Wim)            // 3136
#define NLOG    (HEAD * KK * KK * KK * KK)  // 972
#define SCALE   0.17677669529663687f   // 32^-0.5
#define NCG     (DIM / 4)              // 96 float4 channel groups

#define M_BIG   (Bsz * HWpix)          // 200704
#define M_POOL  (Bsz * LWIN)           // 50176

// ----- scratch (device globals: allocation-free) ---------------------------
__device__ float g_V [(size_t)M_BIG  * DIM];        // value image   [B, HW, DIM]
__device__ float g_XP[(size_t)M_POOL * DIM];        // pooled feats  [B, L,  DIM]
__device__ float g_A [(size_t)M_POOL * NLOG];       // attn logits   [B, L,  972]
__device__ float g_O [(size_t)M_POOL * 9 * DIM];    // per-window out [B, L, 9, DIM]
__device__ float g_YF[(size_t)M_BIG  * DIM];        // folded output [B, HW, DIM]

// ---------------------------------------------------------------------------
// TF32 tensor-core GEMM: C[M,N] = A[M,K] * B[N,K]^T + bias[N]
// Block tile 128x128x32, 8 warps (2 M x 4 N), warp tile 64x32.
// Double-buffered dynamic smem (64 KB), one barrier per k-tile.
// ---------------------------------------------------------------------------

__device__ __forceinline__ unsigned f2tf32(float f) {
    unsigned r;
    asm("cvt.rna.tf32.f32 %0, %1;" : "=r"(r) : "f"(f));
    return r;
}

__device__ __forceinline__ void mma_tf32(float c[4],
                                         const unsigned a[4],
                                         const unsigned b[2]) {
    asm volatile(
        "mma.sync.aligned.m16n8k8.row.col.f32.tf32.tf32.f32 "
        "{%0,%1,%2,%3}, {%4,%5,%6,%7}, {%8,%9}, {%0,%1,%2,%3};"
        : "+f"(c[0]), "+f"(c[1]), "+f"(c[2]), "+f"(c[3])
        : "r"(a[0]), "r"(a[1]), "r"(a[2]), "r"(a[3]),
          "r"(b[0]), "r"(b[1]));
}

#define GBM 128
#define GBN 128
#define GBK 32
#define GEMM_SMEM_BYTES (2 * 8192 * 4)

__global__ __launch_bounds__(256, 1)
void gemm_tf32_kernel(const float* __restrict__ A,
                      const float* __restrict__ B,
                      const float* __restrict__ bias,
                      float* __restrict__ C,
                      int M, int N, int K)
{
    extern __shared__ unsigned smem_dyn[];   // [2][8192]: sA 4096 + sB 4096

    const int tid  = threadIdx.x;
    const int lane = tid & 31;
    const int warp = tid >> 5;
    const int wm   = warp >> 2;
    const int wn   = warp & 3;
    const int g    = lane >> 2;
    const int t    = lane & 3;
    const int bm   = blockIdx.y * GBM;
    const int bn   = blockIdx.x * GBN;

    float acc[4][4][4];
#pragma unroll
    for (int i = 0; i < 4; i++)
#pragma unroll
        for (int j = 0; j < 4; j++)
#pragma unroll
            for (int e = 0; e < 4; e++) acc[i][j][e] = 0.f;

    float4 va[4], vb[4];
    int rA[4], cA[4];
#pragma unroll
    for (int it = 0; it < 4; it++) {
        int f = tid + it * 256;
        rA[it] = f >> 3;
        cA[it] = (f & 7) << 2;
    }

    const int KT = K / GBK;

#pragma unroll
    for (int it = 0; it < 4; it++) {
        va[it] = *reinterpret_cast<const float4*>(
            &A[(size_t)(bm + rA[it]) * K + cA[it]]);
        if (bn + rA[it] < N)
            vb[it] = *reinterpret_cast<const float4*>(
                &B[(size_t)(bn + rA[it]) * K + cA[it]]);
        else
            vb[it] = make_float4(0.f, 0.f, 0.f, 0.f);
    }

    for (int kt = 0; kt < KT; kt++) {
        unsigned* sA = smem_dyn + (kt & 1) * 8192;
        unsigned* sB = sA + 4096;

#pragma unroll
        for (int it = 0; it < 4; it++) {
            int r = rA[it], c4 = cA[it];
            int kstep = c4 >> 3;
            int kh    = (c4 >> 2) & 1;
            {
                int mtile = r >> 4;
                int gg    = r & 7;
                int rh    = (r >> 3) & 1;
                unsigned base = ((kstep * 8 + mtile) * 32 + gg * 4) * 4 + kh * 2 + rh;
                sA[base +  0] = f2tf32(va[it].x);
                sA[base +  4] = f2tf32(va[it].y);
                sA[base +  8] = f2tf32(va[it].z);
                sA[base + 12] = f2tf32(va[it].w);
            }
            {
                int ntile = r >> 3;
                int gg    = r & 7;
                unsigned base = ((kstep * 16 + ntile) * 32 + gg * 4) * 2 + kh;
                sB[base + 0] = f2tf32(vb[it].x);
                sB[base + 2] = f2tf32(vb[it].y);
                sB[base + 4] = f2tf32(vb[it].z);
                sB[base + 6] = f2tf32(vb[it].w);
            }
        }
        __syncthreads();

        if (kt + 1 < KT) {
            int k0 = (kt + 1) * GBK;
#pragma unroll
            for (int it = 0; it < 4; it++) {
                va[it] = *reinterpret_cast<const float4*>(
                    &A[(size_t)(bm + rA[it]) * K + k0 + cA[it]]);
                if (bn + rA[it] < N)
                    vb[it] = *reinterpret_cast<const float4*>(
                        &B[(size_t)(bn + rA[it]) * K + k0 + cA[it]]);
                else
                    vb[it] = make_float4(0.f, 0.f, 0.f, 0.f);
            }
        }

#pragma unroll
        for (int s = 0; s < 4; s++) {
            unsigned af[4][4];
            unsigned bf[4][2];
#pragma unroll
            for (int mt = 0; mt < 4; mt++) {
                const uint4 v = *reinterpret_cast<const uint4*>(
                    &sA[((s * 8 + wm * 4 + mt) * 32 + lane) * 4]);
                af[mt][0] = v.x; af[mt][1] = v.y; af[mt][2] = v.z; af[mt][3] = v.w;
            }
#pragma unroll
            for (int nt = 0; nt < 4; nt++) {
                const uint2 v = *reinterpret_cast<const uint2*>(
                    &sB[((s * 16 + wn * 4 + nt) * 32 + lane) * 2]);
                bf[nt][0] = v.x; bf[nt][1] = v.y;
            }
#pragma unroll
            for (int mt = 0; mt < 4; mt++)
#pragma unroll
                for (int nt = 0; nt < 4; nt++)
                    mma_tf32(acc[mt][nt], af[mt], bf[nt]);
        }
    }

#pragma unroll
    for (int mt = 0; mt < 4; mt++) {
        int row0 = bm + wm * 64 + mt * 16 + g;
#pragma unroll
        for (int nt = 0; nt < 4; nt++) {
            int col = bn + wn * 32 + nt * 8 + 2 * t;
            if (col < N) {
                float bx = 0.f, by = 0.f;
                if (bias) { bx = __ldg(&bias[col]); by = __ldg(&bias[col + 1]); }
                float2 v0 = make_float2(acc[mt][nt][0] + bx, acc[mt][nt][1] + by);
                float2 v1 = make_float2(acc[mt][nt][2] + bx, acc[mt][nt][3] + by);
                *reinterpret_cast<float2*>(&C[(size_t)row0 * N + col])       = v0;
                *reinterpret_cast<float2*>(&C[(size_t)(row0 + 8) * N + col]) = v1;
            }
        }
    }
}

// ---------------------------------------------------------------------------
// 2x2 average pool: x [B, HW, DIM] -> xp [B, L, DIM]
// ---------------------------------------------------------------------------
__global__ void pool_kernel(const float* __restrict__ x, float* __restrict__ xp)
{
    size_t idx = (size_t)blockIdx.x * blockDim.x + threadIdx.x;
    const size_t total = (size_t)M_POOL * DIM;
    if (idx >= total) return;
    int d = (int)(idx % DIM);
    size_t r = idx / DIM;
    int l = (int)(r % LWIN);
    int b = (int)(r / LWIN);
    int oh = l / OUTH, ow = l % OUTH;
    int h = oh * 2, w = ow * 2;
    const float* xb = x + (size_t)b * HWpix * DIM;
    float s = xb[((size_t)(h    ) * Wim + w    ) * DIM + d]
            + xb[((size_t)(h    ) * Wim + w + 1) * DIM + d]
            + xb[((size_t)(h + 1) * Wim + w    ) * DIM + d]
            + xb[((size_t)(h + 1) * Wim + w + 1) * DIM + d];
    xp[idx] = 0.25f * s;
}

// ---------------------------------------------------------------------------
// Fused softmax + per-window attention apply, float4 vectorized. NO atomics.
// One block per (b, l). 288 threads.
// Work items: (i in 0..8) x (cg in 0..95) = 864, 3 per thread.
// o4[b, l, i, cg] = sum_j softmax(A)[head(cg), i, j] * V4[pix(j), cg]
// ---------------------------------------------------------------------------
__global__ __launch_bounds__(288)
void attn_apply_kernel(const float* __restrict__ Alog,
                       const float* __restrict__ V,
                       float* __restrict__ O)
{
    __shared__ float  sAt[NLOG];        // 972 (softmaxed in place)
    __shared__ float4 sV4[9 * NCG];     // 864 float4 = 13.5 KB

    const int bl = blockIdx.x;          // b*784 + l
    const int b  = bl / LWIN;
    const int l  = bl % LWIN;
    const int oh = l / OUTH, ow = l % OUTH;
    const int tid = threadIdx.x;

    // stage logits (pre-scaled)
    const float* arow = Alog + (size_t)bl * NLOG;
    for (int tt = tid; tt < NLOG; tt += 288) sAt[tt] = arow[tt] * SCALE;

    // stage V patch as float4 [j][cg]
    const float* vb = V + (size_t)b * HWpix * DIM;
#pragma unroll
    for (int it = 0; it < 3; it++) {
        int tt = tid + it * 288;        // 0..863
        int j  = tt / NCG, cg = tt % NCG;
        int di = j / KK, dj = j % KK;
        int h2 = oh * 2 - 1 + di;
        int w2 = ow * 2 - 1 + dj;
        float4 vv = make_float4(0.f, 0.f, 0.f, 0.f);
        if (h2 >= 0 && h2 < Him && w2 >= 0 && w2 < Wim)
            vv = *reinterpret_cast<const float4*>(
                &vb[((size_t)h2 * Wim + w2) * DIM + cg * 4]);
        sV4[tt] = vv;
    }
    __syncthreads();

    // softmax over 108 groups of 9
    if (tid < HEAD * 9) {
        float* p = &sAt[tid * 9];
        float v[9], m = -1e30f;
#pragma unroll
        for (int j = 0; j < 9; j++) { v[j] = p[j]; m = fmaxf(m, v[j]); }
        float s = 0.f;
#pragma unroll
        for (int j = 0; j < 9; j++) { v[j] = expf(v[j] - m); s += v[j]; }
        float inv = 1.f / s;
#pragma unroll
        for (int j = 0; j < 9; j++) p[j] = v[j] * inv;
    }
    __syncthreads();

    // apply: 3 items per thread; cg fixed per thread, i varies
    const int cg   = tid % NCG;         // 0..95
    const int i0   = tid / NCG;         // 0..2
    const int head = cg >> 3;           // 32 ch / head = 8 cg
    float* obase = O + (size_t)bl * 9 * DIM + cg * 4;

#pragma unroll
    for (int it = 0; it < 3; it++) {
        const int i = i0 + it * 3;      // 0..8
        const float* ar = &sAt[head * 81 + i * 9];
        float4 acc = make_float4(0.f, 0.f, 0.f, 0.f);
#pragma unroll
        for (int j = 0; j < 9; j++) {
            const float a = ar[j];
            const float4 v = sV4[j * NCG + cg];
            acc.x = fmaf(a, v.x, acc.x);
            acc.y = fmaf(a, v.y, acc.y);
            acc.z = fmaf(a, v.z, acc.z);
            acc.w = fmaf(a, v.w, acc.w);
        }
        *reinterpret_cast<float4*>(obase + (size_t)i * DIM) = acc;
    }
}

// ---------------------------------------------------------------------------
// Gather fold: yf[b, h, w, c] = sum over valid (di,dj) of
//   o[b, oh*28+ow, di*3+dj, c] with oh=(h+1-di)/2, ow=(w+1-dj)/2.
// ---------------------------------------------------------------------------
__global__ void fold_kernel(const float* __restrict__ O, float* __restrict__ Yf)
{
    size_t idx = (size_t)blockIdx.x * blockDim.x + threadIdx.x;
    const size_t total = (size_t)M_BIG * NCG;
    if (idx >= total) return;
    int c4 = (int)(idx % NCG);
    size_t pix = idx / NCG;
    int b = (int)(pix / HWpix);
    int p = (int)(pix % HWpix);
    int h = p / Wim, w = p % Wim;

    float4 acc = make_float4(0.f, 0.f, 0.f, 0.f);
    const float* ob = O + (size_t)b * LWIN * 9 * DIM;
#pragma unroll
    for (int di = 0; di < KK; di++) {
        int hh = h + 1 - di;
        if (hh & 1) continue;
        int oh = hh >> 1;
        if (oh < 0 || oh >= OUTH) continue;
#pragma unroll
        for (int dj = 0; dj < KK; dj++) {
            int ww = w + 1 - dj;
            if (ww & 1) continue;
            int ow = ww >> 1;
            if (ow < 0 || ow >= OUTH) continue;
            const float4 v = *reinterpret_cast<const float4*>(
                &ob[((size_t)(oh * OUTH + ow) * 9 + (di * KK + dj)) * DIM + c4 * 4]);
            acc.x += v.x; acc.y += v.y; acc.z += v.z; acc.w += v.w;
        }
    }
    *reinterpret_cast<float4*>(&Yf[idx * 4]) = acc;
}

// ---------------------------------------------------------------------------
// kernel_launch
// ---------------------------------------------------------------------------
extern "C" void kernel_launch(void* const* d_in, const int* in_sizes, int n_in,
                              void* d_out, int out_size)
{
    const float* x  = (const float*)d_in[0];
    const float* Wv = (const float*)d_in[1];
    const float* Wa = (const float*)d_in[2];
    const float* ba = (const float*)d_in[3];
    const float* Wp = (const float*)d_in[4];
    const float* bp = (const float*)d_in[5];
    float* out = (float*)d_out;

    float *pV, *pXP, *pA, *pO, *pYF;
    cudaGetSymbolAddress((void**)&pV,  g_V);
    cudaGetSymbolAddress((void**)&pXP, g_XP);
    cudaGetSymbolAddress((void**)&pA,  g_A);
    cudaGetSymbolAddress((void**)&pO,  g_O);
    cudaGetSymbolAddress((void**)&pYF, g_YF);

    cudaFuncSetAttribute(gemm_tf32_kernel,
                         cudaFuncAttributeMaxDynamicSharedMemorySize,
                         GEMM_SMEM_BYTES);

    // GEMM1: V = x @ Wv^T           [200704,384] x [384,384]
    gemm_tf32_kernel<<<dim3(DIM / GBN, M_BIG / GBM), 256, GEMM_SMEM_BYTES>>>(
        x, Wv, nullptr, pV, M_BIG, DIM, DIM);

    // pool: xp = avgpool2x2(x)
    {
        size_t total = (size_t)M_POOL * DIM;
        pool_kernel<<<(unsigned)((total + 255) / 256), 256>>>(x, pXP);
    }

    // GEMM2: logits = xp @ Wa^T + ba   [50176,384] x [384,972]
    gemm_tf32_kernel<<<dim3((NLOG + GBN - 1) / GBN, M_POOL / GBM), 256,
                      GEMM_SMEM_BYTES>>>(
        pXP, Wa, ba, pA, M_POOL, NLOG, DIM);

    // fused softmax + attention apply (writes O, no atomics)
    attn_apply_kernel<<<M_POOL, 288>>>(pA, pV, pO);

    // gather fold: O -> Yf
    {
        size_t total = (size_t)M_BIG * NCG;
        fold_kernel<<<(unsigned)((total + 255) / 256), 256>>>(pO, pYF);
    }

    // GEMM3: out = Yf @ Wp^T + bp     [200704,384] x [384,384]
    gemm_tf32_kernel<<<dim3(DIM / GBN, M_BIG / GBM), 256, GEMM_SMEM_BYTES>>>(
        pYF, Wp, bp, out, M_BIG, DIM, DIM);
}